// round 1
// baseline (speedup 1.0000x reference)
#include <cuda_runtime.h>
#include <math.h>

#define BMAX 4
#define NMAX 2048
#define MAXIT 11
#define JC 512
#define TOLD 1e-4

// ---------------- persistent device state (no allocations allowed) ----------
__device__ float g_pc[BMAX * NMAX * 3];                 // temp_pc
__device__ unsigned long long g_pack[BMAX * NMAX];      // (d2_bits<<32)|argmin_j
__device__ double g_H[BMAX][9];
__device__ double g_c1[BMAX][3];
__device__ double g_c2[BMAX][3];
__device__ double g_errpart[BMAX];
__device__ double g_Rm[BMAX][9];
__device__ double g_tv[BMAX][3];
__device__ double g_prev_err;
__device__ int g_flags[MAXIT + 1];

// ---------------- init: temp_pc = p1, reset pack/flags ----------------------
__global__ void init_kernel(const float* __restrict__ p1, int B, int N) {
    int i = blockIdx.x * blockDim.x + threadIdx.x;
    int total = B * N;
    if (i < total) {
        g_pc[i * 3 + 0] = p1[i * 3 + 0];
        g_pc[i * 3 + 1] = p1[i * 3 + 1];
        g_pc[i * 3 + 2] = p1[i * 3 + 2];
        g_pack[i] = ~0ull;
    }
    if (i == 0) {
        g_prev_err = 0.0;
        for (int k = 0; k <= MAXIT; k++) g_flags[k] = 0;
    }
}

// ---------------- NN: for each p2 point, nearest temp_pc point --------------
// grid: (i-chunks, j-chunks, B), 128 threads. Partial argmin per j-chunk,
// combined with atomicMin on packed (d2bits, j). Ties -> smallest j (first
// index), matching jnp.argmin over sqrt(d2) (sqrt is monotone).
__global__ void nn_kernel(const float* __restrict__ p2, int N, int it) {
    if (g_flags[it]) return;
    __shared__ float sx[JC], sy[JC], sz[JC];
    int b = blockIdx.z;
    int j0 = blockIdx.y * JC;
    for (int j = threadIdx.x; j < JC; j += blockDim.x) {
        int jj = j0 + j;
        if (jj < N) {
            const float* p = &g_pc[(b * N + jj) * 3];
            sx[j] = p[0]; sy[j] = p[1]; sz[j] = p[2];
        } else {
            sx[j] = 1e30f; sy[j] = 1e30f; sz[j] = 1e30f;
        }
    }
    __syncthreads();
    int i = blockIdx.x * blockDim.x + threadIdx.x;
    if (i >= N) return;
    const float* q = &p2[(b * N + i) * 3];
    float qx = q[0], qy = q[1], qz = q[2];
    float best = 3.4e38f;
    int bj = 0;
    int jmax = min(JC, N - j0);
#pragma unroll 8
    for (int j = 0; j < jmax; j++) {
        float dx = qx - sx[j], dy = qy - sy[j], dz = qz - sz[j];
        float d2 = fmaf(dx, dx, fmaf(dy, dy, dz * dz));
        if (d2 < best) { best = d2; bj = j0 + j; }
    }
    unsigned long long pk =
        ((unsigned long long)__float_as_uint(best) << 32) |
        (unsigned long long)(unsigned)bj;
    atomicMin(&g_pack[b * N + i], pk);
}

// ---------------- per-batch sums for H (iteration version) ------------------
// q1 = temp_pc, q2 = matched = p2[b, idx_last[n]]; also sums sqrt(d2) for err.
__global__ void hsum_iter(const float* __restrict__ p2, int N, int B, int it) {
    if (g_flags[it]) return;
    int b = blockIdx.x;
    double acc[16];
#pragma unroll
    for (int v = 0; v < 16; v++) acc[v] = 0.0;
    for (int n = threadIdx.x; n < N; n += blockDim.x) {
        const float* pc = &g_pc[(b * N + n) * 3];
        double ax = pc[0], ay = pc[1], az = pc[2];
        unsigned long long pkL = g_pack[(B - 1) * N + n];    // idx[-1]
        int mi = (int)(unsigned)(pkL & 0xFFFFFFFFull);
        const float* m = &p2[(b * N + mi) * 3];
        double bx = m[0], by = m[1], bz = m[2];
        unsigned long long pkb = g_pack[b * N + n];
        float d2 = __uint_as_float((unsigned)(pkb >> 32));
        acc[0] += ax;  acc[1] += ay;  acc[2] += az;          // S1 = sum pc
        acc[3] += bx;  acc[4] += by;  acc[5] += bz;          // S2 = sum matched
        acc[6] += bx * ax;  acc[7] += bx * ay;  acc[8] += bx * az;  // M[j][k]=m[j]*pc[k]
        acc[9] += by * ax;  acc[10] += by * ay; acc[11] += by * az;
        acc[12] += bz * ax; acc[13] += bz * ay; acc[14] += bz * az;
        acc[15] += (double)sqrtf(d2);
    }
    __shared__ double red[256];
    double outv[16];
#pragma unroll
    for (int v = 0; v < 16; v++) {
        red[threadIdx.x] = acc[v];
        __syncthreads();
        for (int s = blockDim.x >> 1; s > 0; s >>= 1) {
            if (threadIdx.x < (unsigned)s) red[threadIdx.x] += red[threadIdx.x + s];
            __syncthreads();
        }
        if (threadIdx.x == 0) outv[v] = red[0];
        __syncthreads();
    }
    if (threadIdx.x == 0) {
        double invN = 1.0 / (double)N;
        double S1[3] = {outv[0], outv[1], outv[2]};
        double S2[3] = {outv[3], outv[4], outv[5]};
#pragma unroll
        for (int j = 0; j < 3; j++)
#pragma unroll
            for (int k = 0; k < 3; k++)
                g_H[b][j * 3 + k] = outv[6 + j * 3 + k] - S2[j] * S1[k] * invN;
#pragma unroll
        for (int k = 0; k < 3; k++) {
            g_c1[b][k] = S1[k] * invN;
            g_c2[b][k] = S2[k] * invN;
        }
        g_errpart[b] = outv[15];
    }
}

// ---------------- per-batch sums for H (final: q1 = p1, q2 = temp_pc) -------
__global__ void hsum_final(const float* __restrict__ p1, int N) {
    int b = blockIdx.x;
    double acc[15];
#pragma unroll
    for (int v = 0; v < 15; v++) acc[v] = 0.0;
    for (int n = threadIdx.x; n < N; n += blockDim.x) {
        const float* a = &p1[(b * N + n) * 3];
        const float* c = &g_pc[(b * N + n) * 3];
        double ax = a[0], ay = a[1], az = a[2];     // q1 source
        double bx = c[0], by = c[1], bz = c[2];     // q2 source
        acc[0] += ax;  acc[1] += ay;  acc[2] += az;
        acc[3] += bx;  acc[4] += by;  acc[5] += bz;
        acc[6] += bx * ax;  acc[7] += bx * ay;  acc[8] += bx * az;
        acc[9] += by * ax;  acc[10] += by * ay; acc[11] += by * az;
        acc[12] += bz * ax; acc[13] += bz * ay; acc[14] += bz * az;
    }
    __shared__ double red[256];
    double outv[15];
#pragma unroll
    for (int v = 0; v < 15; v++) {
        red[threadIdx.x] = acc[v];
        __syncthreads();
        for (int s = blockDim.x >> 1; s > 0; s >>= 1) {
            if (threadIdx.x < (unsigned)s) red[threadIdx.x] += red[threadIdx.x + s];
            __syncthreads();
        }
        if (threadIdx.x == 0) outv[v] = red[0];
        __syncthreads();
    }
    if (threadIdx.x == 0) {
        double invN = 1.0 / (double)N;
        double S1[3] = {outv[0], outv[1], outv[2]};
        double S2[3] = {outv[3], outv[4], outv[5]};
#pragma unroll
        for (int j = 0; j < 3; j++)
#pragma unroll
            for (int k = 0; k < 3; k++)
                g_H[b][j * 3 + k] = outv[6 + j * 3 + k] - S2[j] * S1[k] * invN;
#pragma unroll
        for (int k = 0; k < 3; k++) {
            g_c1[b][k] = S1[k] * invN;
            g_c2[b][k] = S2[k] * invN;
        }
    }
}

// ---------------- Kabsch with exact reference semantics ---------------------
// H = U S V^T (descending). d = sign(det U * det V). V[2][2] *= d.
// RT = U V'^T, R = RT^T, t = c2 - c1 @ R.
__device__ void kabsch3x3(const double* __restrict__ H,
                          const double* __restrict__ c1,
                          const double* __restrict__ c2,
                          double* __restrict__ Rout,
                          double* __restrict__ tout) {
    double A[3][3];
#pragma unroll
    for (int i = 0; i < 3; i++)
#pragma unroll
        for (int j = 0; j < 3; j++)
            A[i][j] = H[0 * 3 + i] * H[0 * 3 + j] +
                      H[1 * 3 + i] * H[1 * 3 + j] +
                      H[2 * 3 + i] * H[2 * 3 + j];
    double V[3][3] = {{1, 0, 0}, {0, 1, 0}, {0, 0, 1}};
#pragma unroll 1
    for (int sweep = 0; sweep < 15; sweep++) {
#pragma unroll
        for (int pi = 0; pi < 3; pi++) {
            const int p = (pi == 2) ? 1 : 0;
            const int q = (pi == 0) ? 1 : 2;
            const int r = 3 - p - q;
            double apq = A[p][q];
            if (fabs(apq) > 1e-300) {
                double theta = (A[q][q] - A[p][p]) / (2.0 * apq);
                double tt = 1.0 / (fabs(theta) + sqrt(theta * theta + 1.0));
                if (theta < 0.0) tt = -tt;
                double cc = 1.0 / sqrt(tt * tt + 1.0);
                double ss = tt * cc;
                double app = A[p][p], aqq = A[q][q];
                A[p][p] = app - tt * apq;
                A[q][q] = aqq + tt * apq;
                A[p][q] = 0.0; A[q][p] = 0.0;
                double arp = A[r][p], arq = A[r][q];
                A[r][p] = cc * arp - ss * arq; A[p][r] = A[r][p];
                A[r][q] = ss * arp + cc * arq; A[q][r] = A[r][q];
#pragma unroll
                for (int k = 0; k < 3; k++) {
                    double vp = V[k][p], vq = V[k][q];
                    V[k][p] = cc * vp - ss * vq;
                    V[k][q] = ss * vp + cc * vq;
                }
            }
        }
    }
    double lam[3] = {A[0][0], A[1][1], A[2][2]};
#define CSWAP_(a, b)                                                       \
    if (lam[a] < lam[b]) {                                                 \
        double tl = lam[a]; lam[a] = lam[b]; lam[b] = tl;                  \
        double t0 = V[0][a]; V[0][a] = V[0][b]; V[0][b] = t0;              \
        double t1 = V[1][a]; V[1][a] = V[1][b]; V[1][b] = t1;              \
        double t2 = V[2][a]; V[2][a] = V[2][b]; V[2][b] = t2;              \
    }
    CSWAP_(0, 1); CSWAP_(0, 2); CSWAP_(1, 2);
#undef CSWAP_
    double U[3][3];
#pragma unroll
    for (int i = 0; i < 3; i++) {
        double ux = H[0] * V[0][i] + H[1] * V[1][i] + H[2] * V[2][i];
        double uy = H[3] * V[0][i] + H[4] * V[1][i] + H[5] * V[2][i];
        double uz = H[6] * V[0][i] + H[7] * V[1][i] + H[8] * V[2][i];
        double nn = sqrt(ux * ux + uy * uy + uz * uz);
        if (nn > 1e-20) {
            U[0][i] = ux / nn; U[1][i] = uy / nn; U[2][i] = uz / nn;
        } else {
            // degenerate smallest singular value: cross of other two columns
            int a = (i + 1) % 3, b2 = (i + 2) % 3;
            U[0][i] = U[1][a] * U[2][b2] - U[2][a] * U[1][b2];
            U[1][i] = U[2][a] * U[0][b2] - U[0][a] * U[2][b2];
            U[2][i] = U[0][a] * U[1][b2] - U[1][a] * U[0][b2];
        }
    }
    double detU = U[0][0] * (U[1][1] * U[2][2] - U[1][2] * U[2][1]) -
                  U[0][1] * (U[1][0] * U[2][2] - U[1][2] * U[2][0]) +
                  U[0][2] * (U[1][0] * U[2][1] - U[1][1] * U[2][0]);
    double detV = V[0][0] * (V[1][1] * V[2][2] - V[1][2] * V[2][1]) -
                  V[0][1] * (V[1][0] * V[2][2] - V[1][2] * V[2][0]) +
                  V[0][2] * (V[1][0] * V[2][1] - V[1][1] * V[2][0]);
    double d = (detU * detV < 0.0) ? -1.0 : 1.0;
    V[2][2] *= d;
    // R[j][k] = RT[k][j] = sum_m U[k][m] * V[j][m]
#pragma unroll
    for (int j = 0; j < 3; j++)
#pragma unroll
        for (int k = 0; k < 3; k++)
            Rout[j * 3 + k] =
                U[k][0] * V[j][0] + U[k][1] * V[j][1] + U[k][2] * V[j][2];
#pragma unroll
    for (int k = 0; k < 3; k++)
        tout[k] = c2[k] - (c1[0] * Rout[0 * 3 + k] +
                           c1[1] * Rout[1 * 3 + k] +
                           c1[2] * Rout[2 * 3 + k]);
}

// ---------------- per-iteration SVD + done-flag update ----------------------
__global__ void svd_iter(int N, int B, int it) {
    int done = g_flags[it];
    if (threadIdx.x == 0) {
        if (done) {
            g_flags[it + 1] = 1;
        } else {
            double s = 0.0;
            for (int b = 0; b < B; b++) s += g_errpart[b];
            double mean = s / (double)(B * N);
            g_flags[it + 1] = (fabs(g_prev_err - mean) < TOLD) ? 1 : 0;
            g_prev_err = mean;
        }
    }
    if (done) return;
    int b = threadIdx.x;
    if (b < B) kabsch3x3(g_H[b], g_c1[b], g_c2[b], g_Rm[b], g_tv[b]);
}

// ---------------- apply transform + reset pack for next iteration -----------
__global__ void apply_kernel(int N, int B, int it) {
    if (g_flags[it]) return;
    int idx = blockIdx.x * blockDim.x + threadIdx.x;
    if (idx >= B * N) return;
    int b = idx / N;
    float* p = &g_pc[idx * 3];
    double x = p[0], y = p[1], z = p[2];
    const double* R = g_Rm[b];
    const double* t = g_tv[b];
    double nx = x * R[0] + y * R[3] + z * R[6] + t[0];
    double ny = x * R[1] + y * R[4] + z * R[7] + t[1];
    double nz = x * R[2] + y * R[5] + z * R[8] + t[2];
    p[0] = (float)nx; p[1] = (float)ny; p[2] = (float)nz;
    g_pack[idx] = ~0ull;
}

// ---------------- final transform -> T = [R | t^T] --------------------------
__global__ void svd_final(int B, float* __restrict__ out) {
    int b = threadIdx.x;
    if (b >= B) return;
    double R[9], t[3];
    kabsch3x3(g_H[b], g_c1[b], g_c2[b], R, t);
#pragma unroll
    for (int j = 0; j < 3; j++) {
        out[b * 12 + j * 4 + 0] = (float)R[j * 3 + 0];
        out[b * 12 + j * 4 + 1] = (float)R[j * 3 + 1];
        out[b * 12 + j * 4 + 2] = (float)R[j * 3 + 2];
        out[b * 12 + j * 4 + 3] = (float)t[j];
    }
}

extern "C" void kernel_launch(void* const* d_in, const int* in_sizes, int n_in,
                              void* d_out, int out_size) {
    const float* p1 = (const float*)d_in[0];
    const float* p2 = (const float*)d_in[1];
    float* out = (float*)d_out;

    int B = out_size / 12;            // T is (B,3,4)
    if (B < 1) B = 1;
    if (B > BMAX) B = BMAX;
    int N = in_sizes[0] / (B * 3);    // points per batch
    if (N > NMAX) N = NMAX;

    int total = B * N;
    int tpb = 256;

    init_kernel<<<(total + tpb - 1) / tpb, tpb>>>(p1, B, N);

    dim3 nn_grid((N + 127) / 128, (N + JC - 1) / JC, B);
    for (int it = 0; it < MAXIT; it++) {
        nn_kernel<<<nn_grid, 128>>>(p2, N, it);
        hsum_iter<<<B, 256>>>(p2, N, B, it);
        svd_iter<<<1, 32>>>(N, B, it);
        apply_kernel<<<(total + tpb - 1) / tpb, tpb>>>(N, B, it);
    }
    hsum_final<<<B, 256>>>(p1, N);
    svd_final<<<1, 32>>>(B, out);
}

// round 2
// speedup vs baseline: 3.6180x; 3.6180x over previous
#include <cuda_runtime.h>
#include <math.h>

#define BMAX 4
#define NMAX 2048
#define MAXIT 11
#define JC 512
#define TOLD 1e-4

// ---------------- persistent device state (no allocations allowed) ----------
__device__ float g_pc[BMAX * NMAX * 3];                 // temp_pc
__device__ unsigned long long g_pack[BMAX * NMAX];      // (d2_bits<<32)|argmin_j
__device__ double g_prev_err;
__device__ int g_flags[MAXIT + 1];

// ---------------- init: temp_pc = p1, reset pack/flags ----------------------
__global__ void init_kernel(const float* __restrict__ p1, int B, int N) {
    int i = blockIdx.x * blockDim.x + threadIdx.x;
    int total = B * N;
    if (i < total) {
        g_pc[i * 3 + 0] = p1[i * 3 + 0];
        g_pc[i * 3 + 1] = p1[i * 3 + 1];
        g_pc[i * 3 + 2] = p1[i * 3 + 2];
        g_pack[i] = ~0ull;
    }
    if (i == 0) {
        g_prev_err = 0.0;
        for (int k = 0; k <= MAXIT; k++) g_flags[k] = 0;
    }
}

// ---------------- NN: for each p2 point, nearest temp_pc point --------------
// grid: (i-chunks, j-chunks, B), 128 threads. Partial argmin per j-chunk,
// combined with atomicMin on packed (d2bits, j). Ties -> smallest j (first
// index), matching jnp.argmin over sqrt(d2) (sqrt is monotone).
__global__ void nn_kernel(const float* __restrict__ p2, int N, int it) {
    if (g_flags[it]) return;
    __shared__ float sx[JC], sy[JC], sz[JC];
    int b = blockIdx.z;
    int j0 = blockIdx.y * JC;
    for (int j = threadIdx.x; j < JC; j += blockDim.x) {
        int jj = j0 + j;
        if (jj < N) {
            const float* p = &g_pc[(b * N + jj) * 3];
            sx[j] = p[0]; sy[j] = p[1]; sz[j] = p[2];
        } else {
            sx[j] = 1e30f; sy[j] = 1e30f; sz[j] = 1e30f;
        }
    }
    __syncthreads();
    int i = blockIdx.x * blockDim.x + threadIdx.x;
    if (i >= N) return;
    const float* q = &p2[(b * N + i) * 3];
    float qx = q[0], qy = q[1], qz = q[2];
    float best = 3.4e38f;
    int bj = 0;
    int jmax = min(JC, N - j0);
#pragma unroll 8
    for (int j = 0; j < jmax; j++) {
        float dx = qx - sx[j], dy = qy - sy[j], dz = qz - sz[j];
        float d2 = fmaf(dx, dx, fmaf(dy, dy, dz * dz));
        if (d2 < best) { best = d2; bj = j0 + j; }
    }
    unsigned long long pk =
        ((unsigned long long)__float_as_uint(best) << 32) |
        (unsigned long long)(unsigned)bj;
    atomicMin(&g_pack[b * N + i], pk);
}

// ---------------- Kabsch (fp32) with exact reference semantics --------------
// H = U S V^T (descending). d = sign(det U * det V). V[2][2] *= d.
// RT = U V'^T, R = RT^T, t = c2 - c1 @ R.
__device__ void kabsch3x3f(const float* __restrict__ H,
                           const float* __restrict__ c1,
                           const float* __restrict__ c2,
                           float* __restrict__ Rout,
                           float* __restrict__ tout) {
    float A[3][3];
#pragma unroll
    for (int i = 0; i < 3; i++)
#pragma unroll
        for (int j = 0; j < 3; j++)
            A[i][j] = H[0 * 3 + i] * H[0 * 3 + j] +
                      H[1 * 3 + i] * H[1 * 3 + j] +
                      H[2 * 3 + i] * H[2 * 3 + j];
    float V[3][3] = {{1, 0, 0}, {0, 1, 0}, {0, 0, 1}};
#pragma unroll 1
    for (int sweep = 0; sweep < 8; sweep++) {
#pragma unroll
        for (int pi = 0; pi < 3; pi++) {
            const int p = (pi == 2) ? 1 : 0;
            const int q = (pi == 0) ? 1 : 2;
            const int r = 3 - p - q;
            float apq = A[p][q];
            if (fabsf(apq) > 1e-30f) {
                float theta = (A[q][q] - A[p][p]) / (2.0f * apq);
                float tt = 1.0f / (fabsf(theta) + sqrtf(theta * theta + 1.0f));
                if (theta < 0.0f) tt = -tt;
                float cc = 1.0f / sqrtf(tt * tt + 1.0f);
                float ss = tt * cc;
                float app = A[p][p], aqq = A[q][q];
                A[p][p] = app - tt * apq;
                A[q][q] = aqq + tt * apq;
                A[p][q] = 0.0f; A[q][p] = 0.0f;
                float arp = A[r][p], arq = A[r][q];
                A[r][p] = cc * arp - ss * arq; A[p][r] = A[r][p];
                A[r][q] = ss * arp + cc * arq; A[q][r] = A[r][q];
#pragma unroll
                for (int k = 0; k < 3; k++) {
                    float vp = V[k][p], vq = V[k][q];
                    V[k][p] = cc * vp - ss * vq;
                    V[k][q] = ss * vp + cc * vq;
                }
            }
        }
    }
    float lam[3] = {A[0][0], A[1][1], A[2][2]};
#define CSWAP_(a, b)                                                       \
    if (lam[a] < lam[b]) {                                                 \
        float tl = lam[a]; lam[a] = lam[b]; lam[b] = tl;                   \
        float t0 = V[0][a]; V[0][a] = V[0][b]; V[0][b] = t0;               \
        float t1 = V[1][a]; V[1][a] = V[1][b]; V[1][b] = t1;               \
        float t2 = V[2][a]; V[2][a] = V[2][b]; V[2][b] = t2;               \
    }
    CSWAP_(0, 1); CSWAP_(0, 2); CSWAP_(1, 2);
#undef CSWAP_
    float U[3][3];
#pragma unroll
    for (int i = 0; i < 3; i++) {
        float ux = H[0] * V[0][i] + H[1] * V[1][i] + H[2] * V[2][i];
        float uy = H[3] * V[0][i] + H[4] * V[1][i] + H[5] * V[2][i];
        float uz = H[6] * V[0][i] + H[7] * V[1][i] + H[8] * V[2][i];
        float nn = sqrtf(ux * ux + uy * uy + uz * uz);
        if (nn > 1e-12f) {
            float inv = 1.0f / nn;
            U[0][i] = ux * inv; U[1][i] = uy * inv; U[2][i] = uz * inv;
        } else {
            // degenerate smallest singular value: cross of other two columns
            int a = (i + 1) % 3, b2 = (i + 2) % 3;
            U[0][i] = U[1][a] * U[2][b2] - U[2][a] * U[1][b2];
            U[1][i] = U[2][a] * U[0][b2] - U[0][a] * U[2][b2];
            U[2][i] = U[0][a] * U[1][b2] - U[1][a] * U[0][b2];
        }
    }
    float detU = U[0][0] * (U[1][1] * U[2][2] - U[1][2] * U[2][1]) -
                 U[0][1] * (U[1][0] * U[2][2] - U[1][2] * U[2][0]) +
                 U[0][2] * (U[1][0] * U[2][1] - U[1][1] * U[2][0]);
    float detV = V[0][0] * (V[1][1] * V[2][2] - V[1][2] * V[2][1]) -
                 V[0][1] * (V[1][0] * V[2][2] - V[1][2] * V[2][0]) +
                 V[0][2] * (V[1][0] * V[2][1] - V[1][1] * V[2][0]);
    float d = (detU * detV < 0.0f) ? -1.0f : 1.0f;
    V[2][2] *= d;
    // R[j][k] = RT[k][j] = sum_m U[k][m] * V[j][m]
#pragma unroll
    for (int j = 0; j < 3; j++)
#pragma unroll
        for (int k = 0; k < 3; k++)
            Rout[j * 3 + k] =
                U[k][0] * V[j][0] + U[k][1] * V[j][1] + U[k][2] * V[j][2];
#pragma unroll
    for (int k = 0; k < 3; k++)
        tout[k] = c2[k] - (c1[0] * Rout[0 * 3 + k] +
                           c1[1] * Rout[1 * 3 + k] +
                           c1[2] * Rout[2 * 3 + k]);
}

// ---------------- fused per-iteration: H-sums + err + SVD + apply -----------
// One block, 1024 threads = 4 batches x 256 threads.
__global__ __launch_bounds__(1024) void iter_kernel(const float* __restrict__ p2,
                                                    int N, int B, int it) {
    __shared__ float sred[32][16];       // per-warp partials
    __shared__ float sR[BMAX][9];
    __shared__ float sT[BMAX][3];
    __shared__ double serr[BMAX];
    int tid = threadIdx.x;
    if (g_flags[it]) {
        if (tid == 0) g_flags[it + 1] = 1;
        return;
    }
    int b = tid >> 8;
    int t = tid & 255;
    float acc[16];
#pragma unroll
    for (int v = 0; v < 16; v++) acc[v] = 0.0f;
    for (int n = t; n < N; n += 256) {
        const float* pc = &g_pc[(b * N + n) * 3];
        float ax = pc[0], ay = pc[1], az = pc[2];
        unsigned long long pkL = g_pack[(B - 1) * N + n];    // idx[-1]
        int mi = (int)(unsigned)(pkL & 0xFFFFFFFFull);
        const float* m = &p2[(b * N + mi) * 3];
        float bx = m[0], by = m[1], bz = m[2];
        unsigned long long pkb = g_pack[b * N + n];
        float d2 = __uint_as_float((unsigned)(pkb >> 32));
        acc[0] += ax;  acc[1] += ay;  acc[2] += az;          // S1 = sum pc
        acc[3] += bx;  acc[4] += by;  acc[5] += bz;          // S2 = sum matched
        acc[6] += bx * ax;  acc[7] += bx * ay;  acc[8] += bx * az;
        acc[9] += by * ax;  acc[10] += by * ay; acc[11] += by * az;
        acc[12] += bz * ax; acc[13] += bz * ay; acc[14] += bz * az;
        acc[15] += sqrtf(d2);
    }
#pragma unroll
    for (int v = 0; v < 16; v++)
#pragma unroll
        for (int off = 16; off > 0; off >>= 1)
            acc[v] += __shfl_down_sync(0xFFFFFFFFu, acc[v], off);
    int w = tid >> 5, lane = tid & 31;
    if (lane == 0)
#pragma unroll
        for (int v = 0; v < 16; v++) sred[w][v] = acc[v];
    __syncthreads();
    if (tid < B) {
        float s[16];
#pragma unroll
        for (int v = 0; v < 16; v++) {
            float sv = 0.0f;
#pragma unroll
            for (int k = 0; k < 8; k++) sv += sred[tid * 8 + k][v];
            s[v] = sv;
        }
        serr[tid] = (double)s[15];
        float invN = 1.0f / (float)N;
        float H[9], c1[3], c2[3];
#pragma unroll
        for (int j = 0; j < 3; j++)
#pragma unroll
            for (int k = 0; k < 3; k++)
                H[j * 3 + k] = s[6 + j * 3 + k] - s[3 + j] * s[k] * invN;
#pragma unroll
        for (int k = 0; k < 3; k++) {
            c1[k] = s[k] * invN;
            c2[k] = s[3 + k] * invN;
        }
        kabsch3x3f(H, c1, c2, sR[tid], sT[tid]);
    }
    __syncthreads();
    if (tid == 0) {
        double ssum = 0.0;
        for (int bb = 0; bb < B; bb++) ssum += serr[bb];
        double mean = ssum / (double)(B * N);
        g_flags[it + 1] = (fabs(g_prev_err - mean) < TOLD) ? 1 : 0;
        g_prev_err = mean;
    }
    // apply transform + reset pack
    for (int bb = 0; bb < B; bb++) {
        const float* R = sR[bb];
        const float* tv = sT[bb];
        for (int n = tid; n < N; n += 1024) {
            float* p = &g_pc[(bb * N + n) * 3];
            float x = p[0], y = p[1], z = p[2];
            p[0] = x * R[0] + y * R[3] + z * R[6] + tv[0];
            p[1] = x * R[1] + y * R[4] + z * R[7] + tv[1];
            p[2] = x * R[2] + y * R[5] + z * R[8] + tv[2];
            g_pack[bb * N + n] = ~0ull;
        }
    }
}

// ---------------- fused final: H-sums (q1=p1, q2=temp_pc) + SVD + output ----
__global__ __launch_bounds__(1024) void final_kernel(const float* __restrict__ p1,
                                                     int N, int B,
                                                     float* __restrict__ out) {
    __shared__ float sred[32][16];
    int tid = threadIdx.x;
    int b = tid >> 8;
    int t = tid & 255;
    float acc[15];
#pragma unroll
    for (int v = 0; v < 15; v++) acc[v] = 0.0f;
    for (int n = t; n < N; n += 256) {
        const float* a = &p1[(b * N + n) * 3];
        const float* c = &g_pc[(b * N + n) * 3];
        float ax = a[0], ay = a[1], az = a[2];     // q1 source
        float bx = c[0], by = c[1], bz = c[2];     // q2 source
        acc[0] += ax;  acc[1] += ay;  acc[2] += az;
        acc[3] += bx;  acc[4] += by;  acc[5] += bz;
        acc[6] += bx * ax;  acc[7] += bx * ay;  acc[8] += bx * az;
        acc[9] += by * ax;  acc[10] += by * ay; acc[11] += by * az;
        acc[12] += bz * ax; acc[13] += bz * ay; acc[14] += bz * az;
    }
#pragma unroll
    for (int v = 0; v < 15; v++)
#pragma unroll
        for (int off = 16; off > 0; off >>= 1)
            acc[v] += __shfl_down_sync(0xFFFFFFFFu, acc[v], off);
    int w = tid >> 5, lane = tid & 31;
    if (lane == 0)
#pragma unroll
        for (int v = 0; v < 15; v++) sred[w][v] = acc[v];
    __syncthreads();
    if (tid < B) {
        float s[15];
#pragma unroll
        for (int v = 0; v < 15; v++) {
            float sv = 0.0f;
#pragma unroll
            for (int k = 0; k < 8; k++) sv += sred[tid * 8 + k][v];
            s[v] = sv;
        }
        float invN = 1.0f / (float)N;
        float H[9], c1[3], c2[3], R[9], tv[3];
#pragma unroll
        for (int j = 0; j < 3; j++)
#pragma unroll
            for (int k = 0; k < 3; k++)
                H[j * 3 + k] = s[6 + j * 3 + k] - s[3 + j] * s[k] * invN;
#pragma unroll
        for (int k = 0; k < 3; k++) {
            c1[k] = s[k] * invN;
            c2[k] = s[3 + k] * invN;
        }
        kabsch3x3f(H, c1, c2, R, tv);
#pragma unroll
        for (int j = 0; j < 3; j++) {
            out[tid * 12 + j * 4 + 0] = R[j * 3 + 0];
            out[tid * 12 + j * 4 + 1] = R[j * 3 + 1];
            out[tid * 12 + j * 4 + 2] = R[j * 3 + 2];
            out[tid * 12 + j * 4 + 3] = tv[j];
        }
    }
}

extern "C" void kernel_launch(void* const* d_in, const int* in_sizes, int n_in,
                              void* d_out, int out_size) {
    const float* p1 = (const float*)d_in[0];
    const float* p2 = (const float*)d_in[1];
    float* out = (float*)d_out;

    int B = out_size / 12;            // T is (B,3,4)
    if (B < 1) B = 1;
    if (B > BMAX) B = BMAX;
    int N = in_sizes[0] / (B * 3);    // points per batch
    if (N > NMAX) N = NMAX;

    int total = B * N;
    int tpb = 256;

    init_kernel<<<(total + tpb - 1) / tpb, tpb>>>(p1, B, N);

    dim3 nn_grid((N + 127) / 128, (N + JC - 1) / JC, B);
    for (int it = 0; it < MAXIT; it++) {
        nn_kernel<<<nn_grid, 128>>>(p2, N, it);
        iter_kernel<<<1, 1024>>>(p2, N, B, it);
    }
    final_kernel<<<1, 1024>>>(p1, N, B, out);
}

// round 3
// speedup vs baseline: 4.7368x; 1.3092x over previous
#include <cuda_runtime.h>
#include <math.h>

#define BMAX 4
#define NMAX 2048
#define MAXIT 11
#define TOLD 1e-4
#define NB 128          // persistent blocks (<= SM count, 1 block/SM resident)
#define NT 512          // threads per block
#define JCH 256         // refs per smem chunk
#define ICH 512         // queries per i-tile (== NT)

// ---------------- persistent device state (no allocations allowed) ----------
__device__ float g_pc[BMAX * NMAX * 3];             // temp_pc
__device__ unsigned long long g_pack[BMAX * NMAX];  // (d2bits<<32)|argmin_j
__device__ float g_R[BMAX][9];
__device__ float g_t[BMAX][3];
__device__ float g_errpart[BMAX];
__device__ double g_prev_err;
__device__ int g_done;
__device__ unsigned g_arrive[2];                    // zero-init; self-resetting
__device__ unsigned g_depart[2];

// ---------------- self-resetting grid barrier (two alternating slots) -------
__device__ __forceinline__ void gbar(int slot) {
    __syncthreads();
    if (threadIdx.x == 0) {
        __threadfence();                       // release + L1 invalidate
        atomicAdd(&g_arrive[slot], 1u);
        while (atomicAdd(&g_arrive[slot], 0u) < (unsigned)NB) __nanosleep(32);
        unsigned d = atomicAdd(&g_depart[slot], 1u) + 1u;
        if (d == (unsigned)NB) {               // last out resets the slot
            atomicExch(&g_arrive[slot], 0u);
            atomicExch(&g_depart[slot], 0u);
        }
        __threadfence();                       // acquire + L1 invalidate
    }
    __syncthreads();
}

// ---------------- Kabsch (fp32) with exact reference semantics --------------
__device__ void kabsch3x3f(const float* __restrict__ H,
                           const float* __restrict__ c1,
                           const float* __restrict__ c2,
                           float* __restrict__ Rout,
                           float* __restrict__ tout) {
    float A[3][3];
#pragma unroll
    for (int i = 0; i < 3; i++)
#pragma unroll
        for (int j = 0; j < 3; j++)
            A[i][j] = H[0 * 3 + i] * H[0 * 3 + j] +
                      H[1 * 3 + i] * H[1 * 3 + j] +
                      H[2 * 3 + i] * H[2 * 3 + j];
    float V[3][3] = {{1, 0, 0}, {0, 1, 0}, {0, 0, 1}};
#pragma unroll 1
    for (int sweep = 0; sweep < 8; sweep++) {
#pragma unroll
        for (int pi = 0; pi < 3; pi++) {
            const int p = (pi == 2) ? 1 : 0;
            const int q = (pi == 0) ? 1 : 2;
            const int r = 3 - p - q;
            float apq = A[p][q];
            if (fabsf(apq) > 1e-30f) {
                float theta = (A[q][q] - A[p][p]) / (2.0f * apq);
                float tt = 1.0f / (fabsf(theta) + sqrtf(theta * theta + 1.0f));
                if (theta < 0.0f) tt = -tt;
                float cc = 1.0f / sqrtf(tt * tt + 1.0f);
                float ss = tt * cc;
                float app = A[p][p], aqq = A[q][q];
                A[p][p] = app - tt * apq;
                A[q][q] = aqq + tt * apq;
                A[p][q] = 0.0f; A[q][p] = 0.0f;
                float arp = A[r][p], arq = A[r][q];
                A[r][p] = cc * arp - ss * arq; A[p][r] = A[r][p];
                A[r][q] = ss * arp + cc * arq; A[q][r] = A[r][q];
#pragma unroll
                for (int k = 0; k < 3; k++) {
                    float vp = V[k][p], vq = V[k][q];
                    V[k][p] = cc * vp - ss * vq;
                    V[k][q] = ss * vp + cc * vq;
                }
            }
        }
    }
    float lam[3] = {A[0][0], A[1][1], A[2][2]};
#define CSWAP_(a, b)                                                       \
    if (lam[a] < lam[b]) {                                                 \
        float tl = lam[a]; lam[a] = lam[b]; lam[b] = tl;                   \
        float t0 = V[0][a]; V[0][a] = V[0][b]; V[0][b] = t0;               \
        float t1 = V[1][a]; V[1][a] = V[1][b]; V[1][b] = t1;               \
        float t2 = V[2][a]; V[2][a] = V[2][b]; V[2][b] = t2;               \
    }
    CSWAP_(0, 1); CSWAP_(0, 2); CSWAP_(1, 2);
#undef CSWAP_
    float U[3][3];
#pragma unroll
    for (int i = 0; i < 3; i++) {
        float ux = H[0] * V[0][i] + H[1] * V[1][i] + H[2] * V[2][i];
        float uy = H[3] * V[0][i] + H[4] * V[1][i] + H[5] * V[2][i];
        float uz = H[6] * V[0][i] + H[7] * V[1][i] + H[8] * V[2][i];
        float nn = sqrtf(ux * ux + uy * uy + uz * uz);
        if (nn > 1e-12f) {
            float inv = 1.0f / nn;
            U[0][i] = ux * inv; U[1][i] = uy * inv; U[2][i] = uz * inv;
        } else {
            int a = (i + 1) % 3, b2 = (i + 2) % 3;
            U[0][i] = U[1][a] * U[2][b2] - U[2][a] * U[1][b2];
            U[1][i] = U[2][a] * U[0][b2] - U[0][a] * U[2][b2];
            U[2][i] = U[0][a] * U[1][b2] - U[1][a] * U[0][b2];
        }
    }
    float detU = U[0][0] * (U[1][1] * U[2][2] - U[1][2] * U[2][1]) -
                 U[0][1] * (U[1][0] * U[2][2] - U[1][2] * U[2][0]) +
                 U[0][2] * (U[1][0] * U[2][1] - U[1][1] * U[2][0]);
    float detV = V[0][0] * (V[1][1] * V[2][2] - V[1][2] * V[2][1]) -
                 V[0][1] * (V[1][0] * V[2][2] - V[1][2] * V[2][0]) +
                 V[0][2] * (V[1][0] * V[2][1] - V[1][1] * V[2][0]);
    float d = (detU * detV < 0.0f) ? -1.0f : 1.0f;
    V[2][2] *= d;
#pragma unroll
    for (int j = 0; j < 3; j++)
#pragma unroll
        for (int k = 0; k < 3; k++)
            Rout[j * 3 + k] =
                U[k][0] * V[j][0] + U[k][1] * V[j][1] + U[k][2] * V[j][2];
#pragma unroll
    for (int k = 0; k < 3; k++)
        tout[k] = c2[k] - (c1[0] * Rout[0 * 3 + k] +
                           c1[1] * Rout[1 * 3 + k] +
                           c1[2] * Rout[2 * 3 + k]);
}

// ---------------- block-level 16-way sum helper (512 threads) ---------------
// acc[NV] per thread -> sfin[NV] (valid in all threads after call)
template <int NV>
__device__ void block_reduce(float* acc, float* sfin, float (*sred)[16]) {
    int tid = threadIdx.x;
#pragma unroll
    for (int v = 0; v < NV; v++)
#pragma unroll
        for (int off = 16; off > 0; off >>= 1)
            acc[v] += __shfl_down_sync(0xFFFFFFFFu, acc[v], off);
    int w = tid >> 5, lane = tid & 31;
    if (lane == 0)
#pragma unroll
        for (int v = 0; v < NV; v++) sred[w][v] = acc[v];
    __syncthreads();
    if (tid < NV) {
        float sv = 0.0f;
#pragma unroll
        for (int k = 0; k < NT / 32; k++) sv += sred[k][tid];
        sfin[tid] = sv;
    }
    __syncthreads();
}

// ---------------- the whole ICP in one persistent kernel --------------------
__global__ __launch_bounds__(NT, 1) void icp_kernel(const float* __restrict__ p1,
                                                    const float* __restrict__ p2,
                                                    float* __restrict__ out,
                                                    int N, int B) {
    __shared__ float4 sref[JCH];
    __shared__ float sred[NT / 32][16];
    __shared__ float sfin[16];
    __shared__ float sRt[BMAX][12];
    int tid = threadIdx.x, blk = blockIdx.x;
    int bs = 0;
    int total = B * N;

    // ---- init: g_pc = p1, pack = inf, scalars ----
    for (int i = blk * NT + tid; i < total; i += NB * NT) {
        g_pc[i * 3 + 0] = p1[i * 3 + 0];
        g_pc[i * 3 + 1] = p1[i * 3 + 1];
        g_pc[i * 3 + 2] = p1[i * 3 + 2];
        g_pack[i] = ~0ull;
    }
    if (blk == 0 && tid == 0) { g_prev_err = 0.0; g_done = 0; }
    gbar(bs); bs ^= 1;

    int nIT = (N + ICH - 1) / ICH;
    int nJC = (N + JCH - 1) / JCH;
    int ntiles = B * nIT * nJC;

    for (int it = 0; it < MAXIT; it++) {
        if (g_done) break;              // uniform: read after barrier

        // ---- NN phase: score = |s|^2 - 2 q.s (monotone in d2) ----
        for (int tile = blk; tile < ntiles; tile += NB) {
            int b = tile / (nIT * nJC);
            int r = tile % (nIT * nJC);
            int ti = r / nJC, tj = r % nJC;
            int j0 = tj * JCH;
            __syncthreads();
            for (int j = tid; j < JCH; j += NT) {
                int jj = j0 + j;
                float4 v;
                if (jj < N) {
                    const float* p = &g_pc[(b * N + jj) * 3];
                    v.x = p[0]; v.y = p[1]; v.z = p[2];
                    v.w = v.x * v.x + v.y * v.y + v.z * v.z;
                } else {
                    v.x = 0.f; v.y = 0.f; v.z = 0.f; v.w = 3.0e38f;
                }
                sref[j] = v;
            }
            __syncthreads();
            int i = ti * ICH + tid;
            if (i < N) {
                const float* q = &p2[(b * N + i) * 3];
                float qx = q[0], qy = q[1], qz = q[2];
                float b0 = 3.4e38f, b1 = 3.4e38f;
                int i0 = 0, i1 = 1;
#pragma unroll 4
                for (int j = 0; j < JCH; j += 2) {
                    float4 s0 = sref[j];
                    float4 s1 = sref[j + 1];
                    float dot0 = fmaf(qx, s0.x, fmaf(qy, s0.y, qz * s0.z));
                    float dot1 = fmaf(qx, s1.x, fmaf(qy, s1.y, qz * s1.z));
                    float sc0 = fmaf(-2.0f, dot0, s0.w);
                    float sc1 = fmaf(-2.0f, dot1, s1.w);
                    if (sc0 < b0) { b0 = sc0; i0 = j; }
                    if (sc1 < b1) { b1 = sc1; i1 = j + 1; }
                }
                int bj = (b1 < b0 || (b1 == b0 && i1 < i0)) ? i1 : i0;
                float4 s = sref[bj];
                float dx = qx - s.x, dy = qy - s.y, dz = qz - s.z;
                float d2 = fmaf(dx, dx, fmaf(dy, dy, dz * dz));
                unsigned long long pk =
                    ((unsigned long long)__float_as_uint(d2) << 32) |
                    (unsigned)(j0 + bj);
                atomicMin(&g_pack[b * N + i], pk);
            }
        }
        gbar(bs); bs ^= 1;

        // ---- hsum + kabsch: blocks 0..B-1, one batch each ----
        if (blk < B) {
            int b = blk;
            float acc[16];
#pragma unroll
            for (int v = 0; v < 16; v++) acc[v] = 0.0f;
            for (int n = tid; n < N; n += NT) {
                const float* pc = &g_pc[(b * N + n) * 3];
                float ax = pc[0], ay = pc[1], az = pc[2];
                unsigned long long pkL = g_pack[(B - 1) * N + n];  // idx[-1]
                int mi = (int)(unsigned)(pkL & 0xFFFFFFFFull);
                const float* m = &p2[(b * N + mi) * 3];
                float bx = m[0], by = m[1], bz = m[2];
                float d2 = __uint_as_float((unsigned)(g_pack[b * N + n] >> 32));
                acc[0] += ax;  acc[1] += ay;  acc[2] += az;
                acc[3] += bx;  acc[4] += by;  acc[5] += bz;
                acc[6] += bx * ax;  acc[7] += bx * ay;  acc[8] += bx * az;
                acc[9] += by * ax;  acc[10] += by * ay; acc[11] += by * az;
                acc[12] += bz * ax; acc[13] += bz * ay; acc[14] += bz * az;
                acc[15] += sqrtf(d2);
            }
            block_reduce<16>(acc, sfin, sred);
            if (tid == 0) {
                float invN = 1.0f / (float)N;
                float H[9], c1[3], c2[3];
#pragma unroll
                for (int j = 0; j < 3; j++)
#pragma unroll
                    for (int k = 0; k < 3; k++)
                        H[j * 3 + k] = sfin[6 + j * 3 + k] -
                                       sfin[3 + j] * sfin[k] * invN;
#pragma unroll
                for (int k = 0; k < 3; k++) {
                    c1[k] = sfin[k] * invN;
                    c2[k] = sfin[3 + k] * invN;
                }
                g_errpart[b] = sfin[15];
                kabsch3x3f(H, c1, c2, g_R[b], g_t[b]);
            }
        }
        gbar(bs); bs ^= 1;

        // ---- apply (all blocks) + done-flag (block0/t0) ----
        if (blk == 0 && tid == 0) {
            double ssum = 0.0;
            for (int bb = 0; bb < B; bb++) ssum += (double)g_errpart[bb];
            double mean = ssum / (double)(B * N);
            g_done = (fabs(g_prev_err - mean) < TOLD) ? 1 : 0;
            g_prev_err = mean;
        }
        if (tid < B * 12) sRt[tid / 12][tid % 12] =
            (tid % 12 < 9) ? g_R[tid / 12][tid % 12] : g_t[tid / 12][tid % 12 - 9];
        __syncthreads();
        for (int idx = blk * NT + tid; idx < total; idx += NB * NT) {
            int b = idx / N;
            const float* R = sRt[b];
            float* p = &g_pc[idx * 3];
            float x = p[0], y = p[1], z = p[2];
            p[0] = x * R[0] + y * R[3] + z * R[6] + R[9];
            p[1] = x * R[1] + y * R[4] + z * R[7] + R[10];
            p[2] = x * R[2] + y * R[5] + z * R[8] + R[11];
            g_pack[idx] = ~0ull;
        }
        gbar(bs); bs ^= 1;
    }

    // ---- final transform: q1 = p1, q2 = temp_pc ----
    if (blk < B) {
        int b = blk;
        float acc[16];
#pragma unroll
        for (int v = 0; v < 16; v++) acc[v] = 0.0f;
        for (int n = tid; n < N; n += NT) {
            const float* a = &p1[(b * N + n) * 3];
            const float* c = &g_pc[(b * N + n) * 3];
            float ax = a[0], ay = a[1], az = a[2];
            float bx = c[0], by = c[1], bz = c[2];
            acc[0] += ax;  acc[1] += ay;  acc[2] += az;
            acc[3] += bx;  acc[4] += by;  acc[5] += bz;
            acc[6] += bx * ax;  acc[7] += bx * ay;  acc[8] += bx * az;
            acc[9] += by * ax;  acc[10] += by * ay; acc[11] += by * az;
            acc[12] += bz * ax; acc[13] += bz * ay; acc[14] += bz * az;
        }
        block_reduce<16>(acc, sfin, sred);
        if (tid == 0) {
            float invN = 1.0f / (float)N;
            float H[9], c1[3], c2[3], R[9], tv[3];
#pragma unroll
            for (int j = 0; j < 3; j++)
#pragma unroll
                for (int k = 0; k < 3; k++)
                    H[j * 3 + k] = sfin[6 + j * 3 + k] -
                                   sfin[3 + j] * sfin[k] * invN;
#pragma unroll
            for (int k = 0; k < 3; k++) {
                c1[k] = sfin[k] * invN;
                c2[k] = sfin[3 + k] * invN;
            }
            kabsch3x3f(H, c1, c2, R, tv);
#pragma unroll
            for (int j = 0; j < 3; j++) {
                out[b * 12 + j * 4 + 0] = R[j * 3 + 0];
                out[b * 12 + j * 4 + 1] = R[j * 3 + 1];
                out[b * 12 + j * 4 + 2] = R[j * 3 + 2];
                out[b * 12 + j * 4 + 3] = tv[j];
            }
        }
    }
}

extern "C" void kernel_launch(void* const* d_in, const int* in_sizes, int n_in,
                              void* d_out, int out_size) {
    const float* p1 = (const float*)d_in[0];
    const float* p2 = (const float*)d_in[1];
    float* out = (float*)d_out;

    int B = out_size / 12;            // T is (B,3,4)
    if (B < 1) B = 1;
    if (B > BMAX) B = BMAX;
    int N = in_sizes[0] / (B * 3);    // points per batch
    if (N > NMAX) N = NMAX;

    icp_kernel<<<NB, NT>>>(p1, p2, out, N, B);
}

// round 5
// speedup vs baseline: 5.2613x; 1.1107x over previous
#include <cuda_runtime.h>
#include <math.h>

#define BMAX 4
#define NMAX 2048
#define MAXIT 11
#define TOLD 1e-4
#define NB 128          // persistent blocks (<= SM count, 1 block/SM resident)
#define NT 512          // threads per block
#define JCH 256         // refs per smem chunk
#define ICH 512         // queries per i-tile (== NT)

// ---------------- persistent device state (no allocations allowed) ----------
__device__ float g_pc[BMAX * NMAX * 3];             // temp_pc
__device__ unsigned long long g_pack[BMAX * NMAX];  // (d2bits<<32)|argmin_j
__device__ float g_R[BMAX][9];
__device__ float g_t[BMAX][3];
__device__ float g_errpart[BMAX];
__device__ double g_prev_err;
__device__ int g_done;
__device__ unsigned g_cnt[3];                       // barrier slots (zero-init)
__device__ unsigned g_dep;

// ---------------- cheap grid barrier: RED arrive + volatile-load poll -------
// Slot rotation 0,1,2,0,... Block 0 resets the previous slot after passing;
// safe because reuse of that slot (3 barriers later) is transitively ordered
// after the fenced reset.
__device__ __forceinline__ void gbar_slot(int s, int blk) {
    __syncthreads();
    if (threadIdx.x == 0) {
        __threadfence();
        atomicAdd(&g_cnt[s], 1u);                   // result unused -> REDG
        while (((volatile unsigned*)g_cnt)[s] < (unsigned)NB) { }
        __threadfence();
        if (blk == 0) g_cnt[(s + 2) % 3] = 0;       // reset previous slot
    }
    __syncthreads();
}

// exit barrier: depart-ack so block0 can reset all counters (graph-replay safe)
__device__ __forceinline__ void gbar_exit(int s, int blk) {
    __syncthreads();
    if (threadIdx.x == 0) {
        __threadfence();
        atomicAdd(&g_cnt[s], 1u);
        while (((volatile unsigned*)g_cnt)[s] < (unsigned)NB) { }
        __threadfence();
        atomicAdd(&g_dep, 1u);
        if (blk == 0) {
            while (*(volatile unsigned*)&g_dep < (unsigned)NB) { }
            g_cnt[0] = 0; g_cnt[1] = 0; g_cnt[2] = 0;
            g_dep = 0;
            __threadfence();
        }
    }
    __syncthreads();
}

// ---------------- Kabsch (fp32) with exact reference semantics --------------
// H = U S V^T (descending). d = sign(det U * det V). V[2][2] *= d.
// RT = U V'^T, R = RT^T, t = c2 - c1 @ R.
__device__ void kabsch3x3f(const float* __restrict__ H,
                           const float* __restrict__ c1,
                           const float* __restrict__ c2,
                           float* __restrict__ Rout,
                           float* __restrict__ tout) {
    float A[3][3];
#pragma unroll
    for (int i = 0; i < 3; i++)
#pragma unroll
        for (int j = 0; j < 3; j++)
            A[i][j] = H[0 * 3 + i] * H[0 * 3 + j] +
                      H[1 * 3 + i] * H[1 * 3 + j] +
                      H[2 * 3 + i] * H[2 * 3 + j];
    float V[3][3] = {{1, 0, 0}, {0, 1, 0}, {0, 0, 1}};
#pragma unroll 1
    for (int sweep = 0; sweep < 8; sweep++) {
#pragma unroll
        for (int pi = 0; pi < 3; pi++) {
            const int p = (pi == 2) ? 1 : 0;
            const int q = (pi == 0) ? 1 : 2;
            const int r = 3 - p - q;
            float apq = A[p][q];
            if (fabsf(apq) > 1e-30f) {
                float theta = (A[q][q] - A[p][p]) / (2.0f * apq);
                float tt = 1.0f / (fabsf(theta) + sqrtf(theta * theta + 1.0f));
                if (theta < 0.0f) tt = -tt;
                float cc = 1.0f / sqrtf(tt * tt + 1.0f);
                float ss = tt * cc;
                float app = A[p][p], aqq = A[q][q];
                A[p][p] = app - tt * apq;
                A[q][q] = aqq + tt * apq;
                A[p][q] = 0.0f; A[q][p] = 0.0f;
                float arp = A[r][p], arq = A[r][q];
                A[r][p] = cc * arp - ss * arq; A[p][r] = A[r][p];
                A[r][q] = ss * arp + cc * arq; A[q][r] = A[r][q];
#pragma unroll
                for (int k = 0; k < 3; k++) {
                    float vp = V[k][p], vq = V[k][q];
                    V[k][p] = cc * vp - ss * vq;
                    V[k][q] = ss * vp + cc * vq;
                }
            }
        }
    }
    float lam[3] = {A[0][0], A[1][1], A[2][2]};
#define CSWAP_(a, b)                                                       \
    if (lam[a] < lam[b]) {                                                 \
        float tl = lam[a]; lam[a] = lam[b]; lam[b] = tl;                   \
        float t0 = V[0][a]; V[0][a] = V[0][b]; V[0][b] = t0;               \
        float t1 = V[1][a]; V[1][a] = V[1][b]; V[1][b] = t1;               \
        float t2 = V[2][a]; V[2][a] = V[2][b]; V[2][b] = t2;               \
    }
    CSWAP_(0, 1); CSWAP_(0, 2); CSWAP_(1, 2);
#undef CSWAP_
    float U[3][3];
#pragma unroll
    for (int i = 0; i < 3; i++) {
        float ux = H[0] * V[0][i] + H[1] * V[1][i] + H[2] * V[2][i];
        float uy = H[3] * V[0][i] + H[4] * V[1][i] + H[5] * V[2][i];
        float uz = H[6] * V[0][i] + H[7] * V[1][i] + H[8] * V[2][i];
        float nn = sqrtf(ux * ux + uy * uy + uz * uz);
        if (nn > 1e-12f) {
            float inv = 1.0f / nn;
            U[0][i] = ux * inv; U[1][i] = uy * inv; U[2][i] = uz * inv;
        } else {
            int a = (i + 1) % 3, b2 = (i + 2) % 3;
            U[0][i] = U[1][a] * U[2][b2] - U[2][a] * U[1][b2];
            U[1][i] = U[2][a] * U[0][b2] - U[0][a] * U[2][b2];
            U[2][i] = U[0][a] * U[1][b2] - U[1][a] * U[0][b2];
        }
    }
    float detU = U[0][0] * (U[1][1] * U[2][2] - U[1][2] * U[2][1]) -
                 U[0][1] * (U[1][0] * U[2][2] - U[1][2] * U[2][0]) +
                 U[0][2] * (U[1][0] * U[2][1] - U[1][1] * U[2][0]);
    float detV = V[0][0] * (V[1][1] * V[2][2] - V[1][2] * V[2][1]) -
                 V[0][1] * (V[1][0] * V[2][2] - V[1][2] * V[2][0]) +
                 V[0][2] * (V[1][0] * V[2][1] - V[1][1] * V[2][0]);
    float d = (detU * detV < 0.0f) ? -1.0f : 1.0f;
    V[2][2] *= d;
#pragma unroll
    for (int j = 0; j < 3; j++)
#pragma unroll
        for (int k = 0; k < 3; k++)
            Rout[j * 3 + k] =
                U[k][0] * V[j][0] + U[k][1] * V[j][1] + U[k][2] * V[j][2];
#pragma unroll
    for (int k = 0; k < 3; k++)
        tout[k] = c2[k] - (c1[0] * Rout[0 * 3 + k] +
                           c1[1] * Rout[1 * 3 + k] +
                           c1[2] * Rout[2 * 3 + k]);
}

// ---------------- block-level 16-way sum helper (512 threads) ---------------
template <int NV>
__device__ void block_reduce(float* acc, float* sfin, float (*sred)[16]) {
    int tid = threadIdx.x;
#pragma unroll
    for (int v = 0; v < NV; v++)
#pragma unroll
        for (int off = 16; off > 0; off >>= 1)
            acc[v] += __shfl_down_sync(0xFFFFFFFFu, acc[v], off);
    int w = tid >> 5, lane = tid & 31;
    if (lane == 0)
#pragma unroll
        for (int v = 0; v < NV; v++) sred[w][v] = acc[v];
    __syncthreads();
    if (tid < NV) {
        float sv = 0.0f;
#pragma unroll
        for (int k = 0; k < NT / 32; k++) sv += sred[k][tid];
        sfin[tid] = sv;
    }
    __syncthreads();
}

// ---------------- the whole ICP in one persistent kernel --------------------
__global__ __launch_bounds__(NT, 1) void icp_kernel(const float* __restrict__ p1,
                                                    const float* __restrict__ p2,
                                                    float* __restrict__ out,
                                                    int N, int B) {
    __shared__ float4 sref[JCH];
    __shared__ float sred[NT / 32][16];
    __shared__ float sfin[16];
    __shared__ float sRt[BMAX][12];
    int tid = threadIdx.x, blk = blockIdx.x;
    int kbar = 0;
    int total = B * N;

    // ---- init: g_pc = p1, pack = inf, scalars ----
    for (int i = blk * NT + tid; i < total; i += NB * NT) {
        g_pc[i * 3 + 0] = p1[i * 3 + 0];
        g_pc[i * 3 + 1] = p1[i * 3 + 1];
        g_pc[i * 3 + 2] = p1[i * 3 + 2];
        g_pack[i] = ~0ull;
    }
    if (blk == 0 && tid == 0) { g_prev_err = 0.0; g_done = 0; }
    gbar_slot(kbar % 3, blk); kbar++;

    int nIT = (N + ICH - 1) / ICH;
    int nJC = (N + JCH - 1) / JCH;
    int ntiles = B * nIT * nJC;

    for (int it = 0; it < MAXIT; it++) {
        if (*(volatile int*)&g_done) break;     // uniform: read after barrier

        // ---- NN phase: score = |s|^2 - 2 q.s (monotone in d2) ----
        for (int tile = blk; tile < ntiles; tile += NB) {
            int b = tile / (nIT * nJC);
            int r = tile % (nIT * nJC);
            int ti = r / nJC, tj = r % nJC;
            int j0 = tj * JCH;
            __syncthreads();                       // smem reuse guard
            for (int j = tid; j < JCH; j += NT) {
                int jj = j0 + j;
                float4 v;
                if (jj < N) {
                    const float* p = &g_pc[(b * N + jj) * 3];
                    v.x = p[0]; v.y = p[1]; v.z = p[2];
                    v.w = v.x * v.x + v.y * v.y + v.z * v.z;
                } else { v.x = 0.f; v.y = 0.f; v.z = 0.f; v.w = 3.0e38f; }
                sref[j] = v;
            }
            __syncthreads();
            int i = ti * ICH + tid;
            if (i < N) {
                const float* q = &p2[(b * N + i) * 3];
                float qx = q[0], qy = q[1], qz = q[2];
                float b0 = 3.4e38f, b1 = 3.4e38f;
                int i0 = 0, i1 = 1;
#pragma unroll 4
                for (int j = 0; j < JCH; j += 2) {
                    float4 s0 = sref[j];
                    float4 s1 = sref[j + 1];
                    float d0 = fmaf(qx, s0.x, fmaf(qy, s0.y, qz * s0.z));
                    float d1 = fmaf(qx, s1.x, fmaf(qy, s1.y, qz * s1.z));
                    float sc0 = fmaf(-2.0f, d0, s0.w);
                    float sc1 = fmaf(-2.0f, d1, s1.w);
                    if (sc0 < b0) { b0 = sc0; i0 = j; }
                    if (sc1 < b1) { b1 = sc1; i1 = j + 1; }
                }
                int bj = (b1 < b0 || (b1 == b0 && i1 < i0)) ? i1 : i0;
                float4 s = sref[bj];
                float dx = qx - s.x, dy = qy - s.y, dz = qz - s.z;
                float d2 = fmaf(dx, dx, fmaf(dy, dy, dz * dz));
                unsigned long long pk =
                    ((unsigned long long)__float_as_uint(d2) << 32) |
                    (unsigned)(j0 + bj);
                atomicMin(&g_pack[b * N + i], pk);
            }
        }
        gbar_slot(kbar % 3, blk); kbar++;

        // ---- hsum + kabsch: blocks 0..B-1, one batch each ----
        if (blk < B) {
            int b = blk;
            float acc[16];
#pragma unroll
            for (int v = 0; v < 16; v++) acc[v] = 0.0f;
            for (int n = tid; n < N; n += NT) {
                const float* pc = &g_pc[(b * N + n) * 3];
                float ax = pc[0], ay = pc[1], az = pc[2];
                unsigned long long pkL = g_pack[(B - 1) * N + n];  // idx[-1]
                int mi = (int)(unsigned)(pkL & 0xFFFFFFFFull);
                const float* m = &p2[(b * N + mi) * 3];
                float bx = m[0], by = m[1], bz = m[2];
                float d2 = __uint_as_float((unsigned)(g_pack[b * N + n] >> 32));
                acc[0] += ax;  acc[1] += ay;  acc[2] += az;
                acc[3] += bx;  acc[4] += by;  acc[5] += bz;
                acc[6] += bx * ax;  acc[7] += bx * ay;  acc[8] += bx * az;
                acc[9] += by * ax;  acc[10] += by * ay; acc[11] += by * az;
                acc[12] += bz * ax; acc[13] += bz * ay; acc[14] += bz * az;
                acc[15] += sqrtf(d2);
            }
            block_reduce<16>(acc, sfin, sred);
            if (tid == 0) {
                float invN = 1.0f / (float)N;
                float H[9], c1[3], c2[3];
#pragma unroll
                for (int j = 0; j < 3; j++)
#pragma unroll
                    for (int k = 0; k < 3; k++)
                        H[j * 3 + k] = sfin[6 + j * 3 + k] -
                                       sfin[3 + j] * sfin[k] * invN;
#pragma unroll
                for (int k = 0; k < 3; k++) {
                    c1[k] = sfin[k] * invN;
                    c2[k] = sfin[3 + k] * invN;
                }
                g_errpart[b] = sfin[15];
                kabsch3x3f(H, c1, c2, g_R[b], g_t[b]);
            }
        }
        gbar_slot(kbar % 3, blk); kbar++;

        // ---- apply (all blocks) + done-flag (block0/t0) ----
        if (blk == 0 && tid == 0) {
            double ssum = 0.0;
            for (int bb = 0; bb < B; bb++) ssum += (double)g_errpart[bb];
            double mean = ssum / (double)(B * N);
            g_done = (fabs(g_prev_err - mean) < TOLD) ? 1 : 0;
            g_prev_err = mean;
        }
        if (tid < B * 12) sRt[tid / 12][tid % 12] =
            (tid % 12 < 9) ? g_R[tid / 12][tid % 12] : g_t[tid / 12][tid % 12 - 9];
        __syncthreads();
        for (int idx = blk * NT + tid; idx < total; idx += NB * NT) {
            int b = idx / N;
            const float* R = sRt[b];
            float* p = &g_pc[idx * 3];
            float x = p[0], y = p[1], z = p[2];
            p[0] = x * R[0] + y * R[3] + z * R[6] + R[9];
            p[1] = x * R[1] + y * R[4] + z * R[7] + R[10];
            p[2] = x * R[2] + y * R[5] + z * R[8] + R[11];
            g_pack[idx] = ~0ull;
        }
        gbar_slot(kbar % 3, blk); kbar++;
    }

    gbar_exit(kbar % 3, blk);   // also resets counters for graph replay

    // ---- final transform: q1 = p1, q2 = temp_pc ----
    if (blk >= B) return;
    {
        int b = blk;
        float acc[16];
#pragma unroll
        for (int v = 0; v < 16; v++) acc[v] = 0.0f;
        for (int n = tid; n < N; n += NT) {
            const float* a = &p1[(b * N + n) * 3];
            const float* c = &g_pc[(b * N + n) * 3];
            float ax = a[0], ay = a[1], az = a[2];
            float bx = c[0], by = c[1], bz = c[2];
            acc[0] += ax;  acc[1] += ay;  acc[2] += az;
            acc[3] += bx;  acc[4] += by;  acc[5] += bz;
            acc[6] += bx * ax;  acc[7] += bx * ay;  acc[8] += bx * az;
            acc[9] += by * ax;  acc[10] += by * ay; acc[11] += by * az;
            acc[12] += bz * ax; acc[13] += bz * ay; acc[14] += bz * az;
        }
        block_reduce<16>(acc, sfin, sred);
        if (tid == 0) {
            float invN = 1.0f / (float)N;
            float H[9], c1[3], c2[3], R[9], tv[3];
#pragma unroll
            for (int j = 0; j < 3; j++)
#pragma unroll
                for (int k = 0; k < 3; k++)
                    H[j * 3 + k] = sfin[6 + j * 3 + k] -
                                   sfin[3 + j] * sfin[k] * invN;
#pragma unroll
            for (int k = 0; k < 3; k++) {
                c1[k] = sfin[k] * invN;
                c2[k] = sfin[3 + k] * invN;
            }
            kabsch3x3f(H, c1, c2, R, tv);
#pragma unroll
            for (int j = 0; j < 3; j++) {
                out[b * 12 + j * 4 + 0] = R[j * 3 + 0];
                out[b * 12 + j * 4 + 1] = R[j * 3 + 1];
                out[b * 12 + j * 4 + 2] = R[j * 3 + 2];
                out[b * 12 + j * 4 + 3] = tv[j];
            }
        }
    }
}

extern "C" void kernel_launch(void* const* d_in, const int* in_sizes, int n_in,
                              void* d_out, int out_size) {
    const float* p1 = (const float*)d_in[0];
    const float* p2 = (const float*)d_in[1];
    float* out = (float*)d_out;

    int B = out_size / 12;            // T is (B,3,4)
    if (B < 1) B = 1;
    if (B > BMAX) B = BMAX;
    int N = in_sizes[0] / (B * 3);    // points per batch
    if (N > NMAX) N = NMAX;

    icp_kernel<<<NB, NT>>>(p1, p2, out, N, B);
}

// round 6
// speedup vs baseline: 5.6662x; 1.0770x over previous
#include <cuda_runtime.h>
#include <math.h>

#define BMAX 4
#define NMAX 2048
#define MAXIT 11
#define TOLD 1e-4
#define NB 128          // persistent blocks (<= SM count, 1 block/SM resident)
#define NT 512          // threads per block
#define QTL 256         // queries per tile
#define RTL 512         // refs per tile
#define RCH 64          // refs per chunk (RTL / 8 chunks)

// ---------------- persistent device state (no allocations allowed) ----------
__device__ float g_pc[BMAX * NMAX * 3];             // temp_pc
__device__ unsigned long long g_pack[BMAX * NMAX];  // (d2bits<<32)|argmin_j
__device__ float g_R[BMAX][9];
__device__ float g_t[BMAX][3];
__device__ float g_errpart[BMAX];
__device__ double g_prev_err;
__device__ int g_done;
__device__ unsigned g_cnt[3];                       // barrier slots (zero-init)
__device__ unsigned g_dep;

// ---------------- cheap grid barrier: RED arrive + volatile-load poll -------
__device__ __forceinline__ void gbar_slot(int s, int blk) {
    __syncthreads();
    if (threadIdx.x == 0) {
        __threadfence();
        atomicAdd(&g_cnt[s], 1u);                   // result unused -> REDG
        while (((volatile unsigned*)g_cnt)[s] < (unsigned)NB) { }
        __threadfence();
        if (blk == 0) g_cnt[(s + 2) % 3] = 0;       // reset previous slot
    }
    __syncthreads();
}

// exit barrier: depart-ack so block0 can reset all counters (graph-replay safe)
__device__ __forceinline__ void gbar_exit(int s, int blk) {
    __syncthreads();
    if (threadIdx.x == 0) {
        __threadfence();
        atomicAdd(&g_cnt[s], 1u);
        while (((volatile unsigned*)g_cnt)[s] < (unsigned)NB) { }
        __threadfence();
        atomicAdd(&g_dep, 1u);
        if (blk == 0) {
            while (*(volatile unsigned*)&g_dep < (unsigned)NB) { }
            g_cnt[0] = 0; g_cnt[1] = 0; g_cnt[2] = 0;
            g_dep = 0;
            __threadfence();
        }
    }
    __syncthreads();
}

// ---------------- Kabsch (fp32) with exact reference semantics --------------
__device__ void kabsch3x3f(const float* __restrict__ H,
                           const float* __restrict__ c1,
                           const float* __restrict__ c2,
                           float* __restrict__ Rout,
                           float* __restrict__ tout) {
    float A[3][3];
#pragma unroll
    for (int i = 0; i < 3; i++)
#pragma unroll
        for (int j = 0; j < 3; j++)
            A[i][j] = H[0 * 3 + i] * H[0 * 3 + j] +
                      H[1 * 3 + i] * H[1 * 3 + j] +
                      H[2 * 3 + i] * H[2 * 3 + j];
    float V[3][3] = {{1, 0, 0}, {0, 1, 0}, {0, 0, 1}};
#pragma unroll 1
    for (int sweep = 0; sweep < 8; sweep++) {
        float offd = A[0][1] * A[0][1] + A[0][2] * A[0][2] + A[1][2] * A[1][2];
        float diag = A[0][0] * A[0][0] + A[1][1] * A[1][1] + A[2][2] * A[2][2];
        if (offd < 1e-13f * diag + 1e-37f) break;   // converged to fp32 eps
#pragma unroll
        for (int pi = 0; pi < 3; pi++) {
            const int p = (pi == 2) ? 1 : 0;
            const int q = (pi == 0) ? 1 : 2;
            const int r = 3 - p - q;
            float apq = A[p][q];
            if (fabsf(apq) > 1e-30f) {
                float theta = (A[q][q] - A[p][p]) / (2.0f * apq);
                float tt = 1.0f / (fabsf(theta) + sqrtf(theta * theta + 1.0f));
                if (theta < 0.0f) tt = -tt;
                float cc = 1.0f / sqrtf(tt * tt + 1.0f);
                float ss = tt * cc;
                float app = A[p][p], aqq = A[q][q];
                A[p][p] = app - tt * apq;
                A[q][q] = aqq + tt * apq;
                A[p][q] = 0.0f; A[q][p] = 0.0f;
                float arp = A[r][p], arq = A[r][q];
                A[r][p] = cc * arp - ss * arq; A[p][r] = A[r][p];
                A[r][q] = ss * arp + cc * arq; A[q][r] = A[r][q];
#pragma unroll
                for (int k = 0; k < 3; k++) {
                    float vp = V[k][p], vq = V[k][q];
                    V[k][p] = cc * vp - ss * vq;
                    V[k][q] = ss * vp + cc * vq;
                }
            }
        }
    }
    float lam[3] = {A[0][0], A[1][1], A[2][2]};
#define CSWAP_(a, b)                                                       \
    if (lam[a] < lam[b]) {                                                 \
        float tl = lam[a]; lam[a] = lam[b]; lam[b] = tl;                   \
        float t0 = V[0][a]; V[0][a] = V[0][b]; V[0][b] = t0;               \
        float t1 = V[1][a]; V[1][a] = V[1][b]; V[1][b] = t1;               \
        float t2 = V[2][a]; V[2][a] = V[2][b]; V[2][b] = t2;               \
    }
    CSWAP_(0, 1); CSWAP_(0, 2); CSWAP_(1, 2);
#undef CSWAP_
    float U[3][3];
#pragma unroll
    for (int i = 0; i < 3; i++) {
        float ux = H[0] * V[0][i] + H[1] * V[1][i] + H[2] * V[2][i];
        float uy = H[3] * V[0][i] + H[4] * V[1][i] + H[5] * V[2][i];
        float uz = H[6] * V[0][i] + H[7] * V[1][i] + H[8] * V[2][i];
        float nn = sqrtf(ux * ux + uy * uy + uz * uz);
        if (nn > 1e-12f) {
            float inv = 1.0f / nn;
            U[0][i] = ux * inv; U[1][i] = uy * inv; U[2][i] = uz * inv;
        } else {
            int a = (i + 1) % 3, b2 = (i + 2) % 3;
            U[0][i] = U[1][a] * U[2][b2] - U[2][a] * U[1][b2];
            U[1][i] = U[2][a] * U[0][b2] - U[0][a] * U[2][b2];
            U[2][i] = U[0][a] * U[1][b2] - U[1][a] * U[0][b2];
        }
    }
    float detU = U[0][0] * (U[1][1] * U[2][2] - U[1][2] * U[2][1]) -
                 U[0][1] * (U[1][0] * U[2][2] - U[1][2] * U[2][0]) +
                 U[0][2] * (U[1][0] * U[2][1] - U[1][1] * U[2][0]);
    float detV = V[0][0] * (V[1][1] * V[2][2] - V[1][2] * V[2][1]) -
                 V[0][1] * (V[1][0] * V[2][2] - V[1][2] * V[2][0]) +
                 V[0][2] * (V[1][0] * V[2][1] - V[1][1] * V[2][0]);
    float d = (detU * detV < 0.0f) ? -1.0f : 1.0f;
    V[2][2] *= d;
#pragma unroll
    for (int j = 0; j < 3; j++)
#pragma unroll
        for (int k = 0; k < 3; k++)
            Rout[j * 3 + k] =
                U[k][0] * V[j][0] + U[k][1] * V[j][1] + U[k][2] * V[j][2];
#pragma unroll
    for (int k = 0; k < 3; k++)
        tout[k] = c2[k] - (c1[0] * Rout[0 * 3 + k] +
                           c1[1] * Rout[1 * 3 + k] +
                           c1[2] * Rout[2 * 3 + k]);
}

// ---------------- block-level 16-way sum helper (512 threads) ---------------
template <int NV>
__device__ void block_reduce(float* acc, float* sfin, float (*sred)[16]) {
    int tid = threadIdx.x;
#pragma unroll
    for (int v = 0; v < NV; v++)
#pragma unroll
        for (int off = 16; off > 0; off >>= 1)
            acc[v] += __shfl_down_sync(0xFFFFFFFFu, acc[v], off);
    int w = tid >> 5, lane = tid & 31;
    if (lane == 0)
#pragma unroll
        for (int v = 0; v < NV; v++) sred[w][v] = acc[v];
    __syncthreads();
    if (tid < NV) {
        float sv = 0.0f;
#pragma unroll
        for (int k = 0; k < NT / 32; k++) sv += sred[k][tid];
        sfin[tid] = sv;
    }
    __syncthreads();
}

// ---------------- the whole ICP in one persistent kernel --------------------
__global__ __launch_bounds__(NT, 1) void icp_kernel(const float* __restrict__ p1,
                                                    const float* __restrict__ p2,
                                                    float* __restrict__ out,
                                                    int N, int B) {
    __shared__ float4 sref[RTL];                    // 8 KB
    __shared__ unsigned long long skey[8][QTL];     // 16 KB
    __shared__ float sred[NT / 32][16];
    __shared__ float sfin[16];
    __shared__ float sRt[BMAX][12];
    int tid = threadIdx.x, blk = blockIdx.x;
    int kbar = 0;
    int total = B * N;

    // ---- init: g_pc = p1, pack = inf, scalars ----
    for (int i = blk * NT + tid; i < total; i += NB * NT) {
        g_pc[i * 3 + 0] = p1[i * 3 + 0];
        g_pc[i * 3 + 1] = p1[i * 3 + 1];
        g_pc[i * 3 + 2] = p1[i * 3 + 2];
        g_pack[i] = ~0ull;
    }
    if (blk == 0 && tid == 0) { g_prev_err = 0.0; g_done = 0; }
    gbar_slot(kbar % 3, blk); kbar++;

    int nIT = (N + QTL - 1) / QTL;
    int nJC = (N + RTL - 1) / RTL;
    int ntiles = B * nIT * nJC;

    for (int it = 0; it < MAXIT; it++) {
        if (*(volatile int*)&g_done) break;     // uniform: read after barrier

        // ---- NN phase: tile = 256 queries x 512 refs; 4 queries/thread ----
        for (int tile = blk; tile < ntiles; tile += NB) {
            int b = tile / (nIT * nJC);
            int r = tile % (nIT * nJC);
            int ti = r / nJC, tj = r % nJC;
            int j0 = tj * RTL;
            __syncthreads();                       // smem reuse guard
            // load refs (x,y,z,|s|^2)
            for (int j = tid; j < RTL; j += NT) {
                int jj = j0 + j;
                float4 v;
                if (jj < N) {
                    const float* p = &g_pc[(b * N + jj) * 3];
                    v.x = p[0]; v.y = p[1]; v.z = p[2];
                    v.w = v.x * v.x + v.y * v.y + v.z * v.z;
                } else { v.x = 0.f; v.y = 0.f; v.z = 0.f; v.w = 3.0e38f; }
                sref[j] = v;
            }
            __syncthreads();

            int qg = tid & 63;                     // query group 0..63
            int c = tid >> 6;                      // ref chunk 0..7
            int i0 = ti * QTL + qg * 4;
            float qx[4], qy[4], qz[4];
            bool qv = (i0 + 3 < N);
            if (qv) {
                // 4 consecutive queries = 48B aligned -> 3x LDG.128
                const float4* qp =
                    (const float4*)&p2[(b * N + i0) * 3];
                float4 a0 = qp[0], a1 = qp[1], a2 = qp[2];
                qx[0] = a0.x; qy[0] = a0.y; qz[0] = a0.z;
                qx[1] = a0.w; qy[1] = a1.x; qz[1] = a1.y;
                qx[2] = a1.z; qy[2] = a1.w; qz[2] = a2.x;
                qx[3] = a2.y; qy[3] = a2.z; qz[3] = a2.w;
            } else {
#pragma unroll
                for (int k = 0; k < 4; k++) {
                    int i = i0 + k;
                    if (i < N) {
                        const float* qq = &p2[(b * N + i) * 3];
                        qx[k] = qq[0]; qy[k] = qq[1]; qz[k] = qq[2];
                    } else { qx[k] = 0.f; qy[k] = 0.f; qz[k] = 0.f; }
                }
            }
            float bs[4] = {3.4e38f, 3.4e38f, 3.4e38f, 3.4e38f};
            int bj[4] = {0, 0, 0, 0};
            int jb = c * RCH;
#pragma unroll 4
            for (int j = 0; j < RCH; j++) {
                float4 s = sref[jb + j];
#pragma unroll
                for (int k = 0; k < 4; k++) {
                    float dot = fmaf(qx[k], s.x, fmaf(qy[k], s.y, qz[k] * s.z));
                    float sc = fmaf(-2.0f, dot, s.w);
                    if (sc < bs[k]) { bs[k] = sc; bj[k] = j; }  // strict: first
                }
            }
#pragma unroll
            for (int k = 0; k < 4; k++) {
                unsigned ub = __float_as_uint(bs[k]);
                ub ^= (ub & 0x80000000u) ? 0xFFFFFFFFu : 0x80000000u;
                skey[c][qg * 4 + k] =
                    ((unsigned long long)ub << 32) | (unsigned)(jb + bj[k]);
            }
            __syncthreads();
            // combine 8 chunks per query; recompute exact d2 for the winner
            if (tid < QTL) {
                int i = ti * QTL + tid;
                if (i < N) {
                    unsigned long long kmin = skey[0][tid];
#pragma unroll
                    for (int cc = 1; cc < 8; cc++) {
                        unsigned long long k2 = skey[cc][tid];
                        if (k2 < kmin) kmin = k2;
                    }
                    int jloc = (int)(unsigned)(kmin & 0xFFFFFFFFull);
                    float4 s = sref[jloc];
                    const float* qq = &p2[(b * N + i) * 3];
                    float dx = qq[0] - s.x, dy = qq[1] - s.y, dz = qq[2] - s.z;
                    float d2 = fmaf(dx, dx, fmaf(dy, dy, dz * dz));
                    unsigned long long pk =
                        ((unsigned long long)__float_as_uint(d2) << 32) |
                        (unsigned)(j0 + jloc);
                    atomicMin(&g_pack[b * N + i], pk);
                }
            }
        }
        gbar_slot(kbar % 3, blk); kbar++;

        // ---- hsum + kabsch: blocks 0..B-1, one batch each ----
        if (blk < B) {
            int b = blk;
            float acc[16];
#pragma unroll
            for (int v = 0; v < 16; v++) acc[v] = 0.0f;
            for (int n = tid; n < N; n += NT) {
                const float* pc = &g_pc[(b * N + n) * 3];
                float ax = pc[0], ay = pc[1], az = pc[2];
                unsigned long long pkL = g_pack[(B - 1) * N + n];  // idx[-1]
                int mi = (int)(unsigned)(pkL & 0xFFFFFFFFull);
                const float* m = &p2[(b * N + mi) * 3];
                float bx = m[0], by = m[1], bz = m[2];
                float d2 = __uint_as_float((unsigned)(g_pack[b * N + n] >> 32));
                acc[0] += ax;  acc[1] += ay;  acc[2] += az;
                acc[3] += bx;  acc[4] += by;  acc[5] += bz;
                acc[6] += bx * ax;  acc[7] += bx * ay;  acc[8] += bx * az;
                acc[9] += by * ax;  acc[10] += by * ay; acc[11] += by * az;
                acc[12] += bz * ax; acc[13] += bz * ay; acc[14] += bz * az;
                acc[15] += sqrtf(d2);
            }
            block_reduce<16>(acc, sfin, sred);
            if (tid == 0) {
                float invN = 1.0f / (float)N;
                float H[9], c1[3], c2[3];
#pragma unroll
                for (int j = 0; j < 3; j++)
#pragma unroll
                    for (int k = 0; k < 3; k++)
                        H[j * 3 + k] = sfin[6 + j * 3 + k] -
                                       sfin[3 + j] * sfin[k] * invN;
#pragma unroll
                for (int k = 0; k < 3; k++) {
                    c1[k] = sfin[k] * invN;
                    c2[k] = sfin[3 + k] * invN;
                }
                g_errpart[b] = sfin[15];
                kabsch3x3f(H, c1, c2, g_R[b], g_t[b]);
            }
        }
        gbar_slot(kbar % 3, blk); kbar++;

        // ---- apply (all blocks) + done-flag (block0/t0) ----
        if (blk == 0 && tid == 0) {
            double ssum = 0.0;
            for (int bb = 0; bb < B; bb++) ssum += (double)g_errpart[bb];
            double mean = ssum / (double)(B * N);
            g_done = (fabs(g_prev_err - mean) < TOLD) ? 1 : 0;
            g_prev_err = mean;
        }
        if (tid < B * 12) sRt[tid / 12][tid % 12] =
            (tid % 12 < 9) ? g_R[tid / 12][tid % 12] : g_t[tid / 12][tid % 12 - 9];
        __syncthreads();
        for (int idx = blk * NT + tid; idx < total; idx += NB * NT) {
            int b = idx / N;
            const float* R = sRt[b];
            float* p = &g_pc[idx * 3];
            float x = p[0], y = p[1], z = p[2];
            p[0] = x * R[0] + y * R[3] + z * R[6] + R[9];
            p[1] = x * R[1] + y * R[4] + z * R[7] + R[10];
            p[2] = x * R[2] + y * R[5] + z * R[8] + R[11];
            g_pack[idx] = ~0ull;
        }
        gbar_slot(kbar % 3, blk); kbar++;
    }

    gbar_exit(kbar % 3, blk);   // also resets counters for graph replay

    // ---- final transform: q1 = p1, q2 = temp_pc ----
    if (blk >= B) return;
    {
        int b = blk;
        float acc[16];
#pragma unroll
        for (int v = 0; v < 16; v++) acc[v] = 0.0f;
        for (int n = tid; n < N; n += NT) {
            const float* a = &p1[(b * N + n) * 3];
            const float* c = &g_pc[(b * N + n) * 3];
            float ax = a[0], ay = a[1], az = a[2];
            float bx = c[0], by = c[1], bz = c[2];
            acc[0] += ax;  acc[1] += ay;  acc[2] += az;
            acc[3] += bx;  acc[4] += by;  acc[5] += bz;
            acc[6] += bx * ax;  acc[7] += bx * ay;  acc[8] += bx * az;
            acc[9] += by * ax;  acc[10] += by * ay; acc[11] += by * az;
            acc[12] += bz * ax; acc[13] += bz * ay; acc[14] += bz * az;
        }
        block_reduce<16>(acc, sfin, sred);
        if (tid == 0) {
            float invN = 1.0f / (float)N;
            float H[9], c1[3], c2[3], R[9], tv[3];
#pragma unroll
            for (int j = 0; j < 3; j++)
#pragma unroll
                for (int k = 0; k < 3; k++)
                    H[j * 3 + k] = sfin[6 + j * 3 + k] -
                                   sfin[3 + j] * sfin[k] * invN;
#pragma unroll
            for (int k = 0; k < 3; k++) {
                c1[k] = sfin[k] * invN;
                c2[k] = sfin[3 + k] * invN;
            }
            kabsch3x3f(H, c1, c2, R, tv);
#pragma unroll
            for (int j = 0; j < 3; j++) {
                out[b * 12 + j * 4 + 0] = R[j * 3 + 0];
                out[b * 12 + j * 4 + 1] = R[j * 3 + 1];
                out[b * 12 + j * 4 + 2] = R[j * 3 + 2];
                out[b * 12 + j * 4 + 3] = tv[j];
            }
        }
    }
}

extern "C" void kernel_launch(void* const* d_in, const int* in_sizes, int n_in,
                              void* d_out, int out_size) {
    const float* p1 = (const float*)d_in[0];
    const float* p2 = (const float*)d_in[1];
    float* out = (float*)d_out;

    int B = out_size / 12;            // T is (B,3,4)
    if (B < 1) B = 1;
    if (B > BMAX) B = BMAX;
    int N = in_sizes[0] / (B * 3);    // points per batch
    if (N > NMAX) N = NMAX;

    icp_kernel<<<NB, NT>>>(p1, p2, out, N, B);
}